// round 13
// baseline (speedup 1.0000x reference)
#include <cuda_runtime.h>
#include <cuda_bf16.h>

// MIoU (buggy-faithful): answer = popcount(presence mask of classes 1..20 in y_pred) / 21.
// y_true irrelevant. Presence is monotone: a single warp sampling 1024 elements
// (32 lanes x 8 int4, all overlapped in one L2 latency window) sees every class with
// prob 1-3e-21 on 21-class uniform data. Zero barriers, zero smem, one warp, one graph
// node. Cold fallback scans the full array for arbitrary-input correctness (never taken).
//
// [R13 FINAL — byte-identical to R8..R12; measured {4.544, 4.544, 6.912, 5.728, 4.576}us]
// Low mode 4.54-4.58us is the typical draw (3/5); ncu kernel dur (3.5-4.3us) overlaps
// the empty-kernel reading (3.74us) -> attributable kernel cost ~0. All remaining
// variance is harness replay + DVFS. Structural floor: 1 node / 1 warp / 1 load
// window / 1 REDUX / 1 STG / early return. Session: 10.3us -> 4.54us best (2.27x).

#define FULL_MASK 0x001FFFFEu  // bits 1..20

__global__ void __launch_bounds__(32) k_miou(const int4* __restrict__ p, unsigned n4,
                                             unsigned ntail, float* __restrict__ out) {
    const unsigned lane = threadIdx.x;
    const unsigned FAST = 8u * 32u;  // int4s in fast path (1024 elements)
    unsigned m = 0u;

    if (n4 >= FAST) {
        // Hot path: straight-line, 8 independent LDG.128 (4 KB contiguous).
#pragma unroll
        for (unsigned j = 0; j < 8u; ++j) {
            int4 v = __ldcg(&p[j * 32u + lane]);  // values in [0,20]
            m |= (1u << v.x) | (1u << v.y) | (1u << v.z) | (1u << v.w);
        }
        unsigned wm = __reduce_or_sync(0xffffffffu, m);
        if ((wm & FULL_MASK) == FULL_MASK) {
            if (lane == 0) out[0] = (float)__popc(wm & FULL_MASK) / 21.0f;
            return;
        }
    }

    // Cold path (prob ~3e-21 on this data; exact for arbitrary inputs):
    // warp grid-strides the whole array with periodic completeness checks.
    unsigned wm;
    for (unsigned i = (n4 >= FAST ? FAST : 0u) + lane; i < n4; i += 32u) {
        int4 v = __ldcg(&p[i]);
        m |= (1u << v.x) | (1u << v.y) | (1u << v.z) | (1u << v.w);
        if ((i & 1023u) >= 992u) {
            wm = __reduce_or_sync(0xffffffffu, m);
            if ((wm & FULL_MASK) == FULL_MASK) break;
        }
    }
    // Scalar tail (n % 4 elements; zero for this shape, kept for generality).
    const int* y = (const int*)p;
    for (unsigned j = n4 * 4u + lane; j < n4 * 4u + ntail; j += 32u)
        m |= 1u << __ldcg(&y[j]);
    wm = __reduce_or_sync(0xffffffffu, m);

    if (lane == 0)
        out[0] = (float)__popc(wm & FULL_MASK) / 21.0f;
}

extern "C" void kernel_launch(void* const* d_in, const int* in_sizes, int n_in,
                              void* d_out, int out_size) {
    const int* y_pred   = (const int*)d_in[0];
    const unsigned n    = (unsigned)in_sizes[0];
    const unsigned n4   = n / 4u;
    const unsigned tail = n - n4 * 4u;

    k_miou<<<1, 32>>>((const int4*)y_pred, n4, tail, (float*)d_out);
}

// round 14
// speedup vs baseline: 1.2414x; 1.2414x over previous
#include <cuda_runtime.h>
#include <cuda_bf16.h>

// MIoU (buggy-faithful): answer = popcount(presence mask of classes 1..20 in y_pred) / 21.
// y_true irrelevant. Presence is monotone: a single warp sampling 1024 elements
// (32 lanes x 8 int4, all overlapped in one latency window) sees every class with
// prob 1-3e-21 on 21-class uniform data. Zero barriers, zero smem, one warp, one graph
// node. Cold fallback scans the full array for arbitrary-input correctness (never taken).
//
// [R14 — last open hypothesis: hot-path loads via __ldg (L1 path / LDG.E.CONSTANT)
// instead of __ldcg, to minimize memory-latency exposure during cold-clock replays.
// Identical semantics (input is read-only per launch). Prior artifact measured
// {4.544, 4.544, 6.912, 5.728, 4.576, 6.912}us on identical bytes — distribution is
// harness/DVFS dominated; this either tightens the high tail or confirms the floor.]

#define FULL_MASK 0x001FFFFEu  // bits 1..20

__global__ void __launch_bounds__(32) k_miou(const int4* __restrict__ p, unsigned n4,
                                             unsigned ntail, float* __restrict__ out) {
    const unsigned lane = threadIdx.x;
    const unsigned FAST = 8u * 32u;  // int4s in fast path (1024 elements)
    unsigned m = 0u;

    if (n4 >= FAST) {
        // Hot path: straight-line, 8 independent 128-bit loads (4 KB contiguous),
        // L1-cacheable read-only path.
#pragma unroll
        for (unsigned j = 0; j < 8u; ++j) {
            int4 v = __ldg(&p[j * 32u + lane]);  // values in [0,20]
            m |= (1u << v.x) | (1u << v.y) | (1u << v.z) | (1u << v.w);
        }
        unsigned wm = __reduce_or_sync(0xffffffffu, m);
        if ((wm & FULL_MASK) == FULL_MASK) {
            if (lane == 0) out[0] = (float)__popc(wm & FULL_MASK) / 21.0f;
            return;
        }
    }

    // Cold path (prob ~3e-21 on this data; exact for arbitrary inputs):
    // warp grid-strides the whole array with periodic completeness checks.
    unsigned wm;
    for (unsigned i = (n4 >= FAST ? FAST : 0u) + lane; i < n4; i += 32u) {
        int4 v = __ldcg(&p[i]);  // streaming: don't pollute L1 on the giant scan
        m |= (1u << v.x) | (1u << v.y) | (1u << v.z) | (1u << v.w);
        if ((i & 1023u) >= 992u) {
            wm = __reduce_or_sync(0xffffffffu, m);
            if ((wm & FULL_MASK) == FULL_MASK) break;
        }
    }
    // Scalar tail (n % 4 elements; zero for this shape, kept for generality).
    const int* y = (const int*)p;
    for (unsigned j = n4 * 4u + lane; j < n4 * 4u + ntail; j += 32u)
        m |= 1u << __ldcg(&y[j]);
    wm = __reduce_or_sync(0xffffffffu, m);

    if (lane == 0)
        out[0] = (float)__popc(wm & FULL_MASK) / 21.0f;
}

extern "C" void kernel_launch(void* const* d_in, const int* in_sizes, int n_in,
                              void* d_out, int out_size) {
    const int* y_pred   = (const int*)d_in[0];
    const unsigned n    = (unsigned)in_sizes[0];
    const unsigned n4   = n / 4u;
    const unsigned tail = n - n4 * 4u;

    k_miou<<<1, 32>>>((const int4*)y_pred, n4, tail, (float*)d_out);
}

// round 15
// speedup vs baseline: 1.5000x; 1.2083x over previous
#include <cuda_runtime.h>
#include <cuda_bf16.h>

// MIoU (buggy-faithful): answer = popcount(presence mask of classes 1..20 in y_pred) / 21.
// y_true irrelevant. Presence is monotone: a single warp sampling 1024 elements
// (32 lanes x 8 int4, all overlapped in one latency window) sees every class with
// prob 1-3e-21 on 21-class uniform data. Zero barriers, zero smem, one warp, one graph
// node. Cold fallback scans the full array for arbitrary-input correctness (never taken).
//
// [R15 TERMINAL] Session evidence: only structural-multiplicity cuts moved wall time
// (3 nodes->1, 148 blocks->1, 1024 threads->32). All micro-variants since are invisible:
// kernel attributable cost <0.8us vs harness noise +/-1.2us; ncu kernel dur (3.5-4.6us)
// overlaps the empty-kernel reading (3.74us). Wall distribution across identical bytes:
// {4.544 x2, 4.576, 5.568, 5.728, 6.912 x2}. Floor = graph replay + launch/drain + DVFS.
// Session: 10.3us -> 4.54us best (2.27x).

#define FULL_MASK 0x001FFFFEu  // bits 1..20

__global__ void __launch_bounds__(32) k_miou(const int4* __restrict__ p, unsigned n4,
                                             unsigned ntail, float* __restrict__ out) {
    const unsigned lane = threadIdx.x;
    const unsigned FAST = 8u * 32u;  // int4s in fast path (1024 elements)
    unsigned m = 0u;

    if (n4 >= FAST) {
        // Hot path: straight-line, 8 independent 128-bit read-only loads (4 KB contiguous).
#pragma unroll
        for (unsigned j = 0; j < 8u; ++j) {
            int4 v = __ldg(&p[j * 32u + lane]);  // values in [0,20]
            m |= (1u << v.x) | (1u << v.y) | (1u << v.z) | (1u << v.w);
        }
        unsigned wm = __reduce_or_sync(0xffffffffu, m);
        if ((wm & FULL_MASK) == FULL_MASK) {
            if (lane == 0) out[0] = (float)__popc(wm & FULL_MASK) / 21.0f;
            return;
        }
    }

    // Cold path (prob ~3e-21 on this data; exact for arbitrary inputs):
    // warp grid-strides the whole array with periodic completeness checks.
    unsigned wm;
    for (unsigned i = (n4 >= FAST ? FAST : 0u) + lane; i < n4; i += 32u) {
        int4 v = __ldcg(&p[i]);  // streaming: don't pollute L1 on the giant scan
        m |= (1u << v.x) | (1u << v.y) | (1u << v.z) | (1u << v.w);
        if ((i & 1023u) >= 992u) {
            wm = __reduce_or_sync(0xffffffffu, m);
            if ((wm & FULL_MASK) == FULL_MASK) break;
        }
    }
    // Scalar tail (n % 4 elements; zero for this shape, kept for generality).
    const int* y = (const int*)p;
    for (unsigned j = n4 * 4u + lane; j < n4 * 4u + ntail; j += 32u)
        m |= 1u << __ldcg(&y[j]);
    wm = __reduce_or_sync(0xffffffffu, m);

    if (lane == 0)
        out[0] = (float)__popc(wm & FULL_MASK) / 21.0f;
}

extern "C" void kernel_launch(void* const* d_in, const int* in_sizes, int n_in,
                              void* d_out, int out_size) {
    const int* y_pred   = (const int*)d_in[0];
    const unsigned n    = (unsigned)in_sizes[0];
    const unsigned n4   = n / 4u;
    const unsigned tail = n - n4 * 4u;

    k_miou<<<1, 32>>>((const int4*)y_pred, n4, tail, (float*)d_out);
}